// round 3
// baseline (speedup 1.0000x reference)
#include <cuda_runtime.h>
#include <math.h>

#define BATCH 2048
#define LIN   70
#define DINC  15
#define HID   16
#define NF    4
#define KW    40
#define LP    31            // 70 - 40 + 1
#define CCH   20            // DIN + 1 + NF
#define SIGCH 8420          // 20 + 400 + 8000
#define NOUT  128
#define Z0    64
#define SPLITK 8
#define KCHUNK 1056         // divisible by 32 and 4; 8*1056 >= 8420

// scratch (static device allocations are the sanctioned workaround)
__device__ float g_sig[(size_t)BATCH * SIGCH];            // ~69 MB
__device__ float g_zpart[(size_t)SPLITK * BATCH * NOUT];  // 8 MB

// ---------------------------------------------------------------------------
// Kernel 1: fused conv stack + path build + depth-3 signature. 1 CTA / batch.
// ---------------------------------------------------------------------------
__global__ __launch_bounds__(512) void sig_kernel(
    const float* __restrict__ x,    // (B, 70, 15)
    const float* __restrict__ w1,   // (16, 15, 40)
    const float* __restrict__ b1,   // (16)
    const float* __restrict__ w2,   // (16, 16)
    const float* __restrict__ b2,   // (16)
    const float* __restrict__ w3,   // (4, 16)
    const float* __restrict__ b3)   // (4)
{
    __shared__ float sw1[HID * DINC * KW];   // 9600 floats
    __shared__ float sx[LIN * DINC];         // 1050
    __shared__ float sh1[HID * LP];          // 496
    __shared__ float sh2[HID * LP];          // 496
    __shared__ float spath[LP * CCH];        // 620
    __shared__ __align__(16) float sd[CCH];  // 20
    __shared__ float ss1[CCH];               // 20

    const int b   = blockIdx.x;
    const int tid = threadIdx.x;

    // stage weights + input into smem
    for (int i = tid; i < HID * DINC * KW; i += 512) sw1[i] = w1[i];
    const float* xb = x + (size_t)b * (LIN * DINC);
    for (int i = tid; i < LIN * DINC; i += 512) sx[i] = xb[i];
    if (tid < CCH) ss1[tid] = 0.f;
    __syncthreads();

    // conv1: h1[o,l] = b1[o] + sum_{k,c} x[l+k,c] * w1[o,c,k]
    if (tid < HID * LP) {
        const int o = tid / LP, l = tid % LP;
        float acc = __ldg(&b1[o]);
        const float* wo = sw1 + o * (DINC * KW);
        #pragma unroll 5
        for (int k = 0; k < KW; k++) {
            const float* xr = sx + (l + k) * DINC;
            const float* wr = wo + k;
            #pragma unroll
            for (int c = 0; c < DINC; c++)
                acc = fmaf(xr[c], wr[c * KW], acc);
        }
        sh1[o * LP + l] = acc;
    }
    __syncthreads();

    // conv2 (pointwise over relu(h1))
    if (tid < HID * LP) {
        const int o = tid / LP, l = tid % LP;
        float acc = __ldg(&b2[o]);
        #pragma unroll
        for (int c = 0; c < HID; c++)
            acc = fmaf(__ldg(&w2[o * HID + c]), fmaxf(sh1[c * LP + l], 0.f), acc);
        sh2[o * LP + l] = acc;
    }
    __syncthreads();

    // conv3 + path assembly: path[l, ch]
    for (int idx = tid; idx < LP * CCH; idx += 512) {
        const int l = idx / CCH, ch = idx % CCH;
        float v;
        if (ch < DINC) {
            v = sx[(KW - 1 + l) * DINC + ch];
        } else if (ch == DINC) {
            v = (float)l * (1.0f / (float)(LP - 1));
        } else {
            const int f = ch - DINC - 1;
            float acc = __ldg(&b3[f]);
            #pragma unroll
            for (int c = 0; c < HID; c++)
                acc = fmaf(__ldg(&w3[f * HID + c]), fmaxf(sh2[c * LP + l], 0.f), acc);
            v = acc;
        }
        spath[idx] = v;
    }
    __syncthreads();

    // depth-3 signature: thread (i,j) owns s2[i,j] (reg) and s3[i,j,0..19] (regs)
    float s3r[CCH];
    #pragma unroll
    for (int k = 0; k < CCH; k++) s3r[k] = 0.f;
    float s2r = 0.f;
    const int ii = tid / CCH;
    const int jj = tid % CCH;

    for (int t = 0; t < LP; t++) {
        if (tid < CCH)
            sd[tid] = spath[t * CCH + tid] - (t ? spath[(t - 1) * CCH + tid] : 0.f);
        __syncthreads();
        if (tid < CCH * CCH) {
            const float di  = sd[ii];
            const float dj  = sd[jj];
            const float s1i = ss1[ii];
            // t2 = s2 + dj*(0.5*s1_i + di/6)
            const float t2 = fmaf(dj, fmaf(di, (1.f / 6.f), 0.5f * s1i), s2r);
            const float4* dv = (const float4*)sd;
            #pragma unroll
            for (int q = 0; q < 5; q++) {
                float4 d4 = dv[q];
                s3r[q * 4 + 0] = fmaf(d4.x, t2, s3r[q * 4 + 0]);
                s3r[q * 4 + 1] = fmaf(d4.y, t2, s3r[q * 4 + 1]);
                s3r[q * 4 + 2] = fmaf(d4.z, t2, s3r[q * 4 + 2]);
                s3r[q * 4 + 3] = fmaf(d4.w, t2, s3r[q * 4 + 3]);
            }
            // n2 = s2 + dj*(s1_i + 0.5*di)
            s2r = fmaf(dj, fmaf(0.5f, di, s1i), s2r);
        }
        __syncthreads();
        if (tid < CCH) ss1[tid] += sd[tid];
    }
    __syncthreads();

    // emit signature row: [s1 (20) | s2 (400, i-major) | s3 (8000, (i,j)-major)]
    float* sig = g_sig + (size_t)b * SIGCH;
    if (tid < CCH) sig[tid] = ss1[tid];
    if (tid < CCH * CCH) {
        sig[CCH + tid] = s2r;  // offset 20 + i*20 + j
        float4* dst = (float4*)(sig + CCH + CCH * CCH + tid * CCH);
        const float4* src = (const float4*)s3r;
        #pragma unroll
        for (int q = 0; q < 5; q++) dst[q] = src[q];
    }
}

// ---------------------------------------------------------------------------
// Kernel 2: split-K GEMM  z_part[s] = sig[m0:m0+64, ks] @ W[:, ks]^T
// BM=64, BN=128 (full), BK=32, 256 threads, thread tile 8x4.
// ---------------------------------------------------------------------------
#define BM 64
#define BK 32

__global__ __launch_bounds__(256) void gemm_kernel(const float* __restrict__ W)
{
    __shared__ float As[BM * 33];    // [m][k], pad 33
    __shared__ float Ws[BK * 132];   // [k][o], pad 132

    const int m0  = blockIdx.x * BM;
    const int s   = blockIdx.y;
    const int kk0 = s * KCHUNK;
    const int kend = min(kk0 + KCHUNK, SIGCH);
    const int tid = threadIdx.x;
    const int mg  = tid >> 5;    // 0..7 -> rows mg*8 .. mg*8+7
    const int ng  = tid & 31;    // 0..31 -> cols ng*4 .. ng*4+3

    float acc[8][4];
    #pragma unroll
    for (int i = 0; i < 8; i++)
        #pragma unroll
        for (int j = 0; j < 4; j++) acc[i][j] = 0.f;

    for (int kk = kk0; kk < kend; kk += BK) {
        // A tile: 64 rows x 8 float4 cols = 512 float4
        #pragma unroll
        for (int u = 0; u < 2; u++) {
            const int idx = tid + u * 256;
            const int r = idx >> 3, q = idx & 7;
            const int c = kk + q * 4;
            float4 v = make_float4(0.f, 0.f, 0.f, 0.f);
            if (c < kend)
                v = *(const float4*)(g_sig + (size_t)(m0 + r) * SIGCH + c);
            As[r * 33 + q * 4 + 0] = v.x;
            As[r * 33 + q * 4 + 1] = v.y;
            As[r * 33 + q * 4 + 2] = v.z;
            As[r * 33 + q * 4 + 3] = v.w;
        }
        // W tile: 128 rows x 8 float4 cols = 1024 float4, stored transposed [k][o]
        #pragma unroll
        for (int u = 0; u < 4; u++) {
            const int idx = tid + u * 256;
            const int o = idx >> 3, q = idx & 7;
            const int c = kk + q * 4;
            float4 v = make_float4(0.f, 0.f, 0.f, 0.f);
            if (c < kend)
                v = *(const float4*)(W + (size_t)o * SIGCH + c);
            Ws[(q * 4 + 0) * 132 + o] = v.x;
            Ws[(q * 4 + 1) * 132 + o] = v.y;
            Ws[(q * 4 + 2) * 132 + o] = v.z;
            Ws[(q * 4 + 3) * 132 + o] = v.w;
        }
        __syncthreads();

        #pragma unroll 8
        for (int k = 0; k < BK; k++) {
            const float4 b4 = *(const float4*)&Ws[k * 132 + ng * 4];
            float a[8];
            #pragma unroll
            for (int i = 0; i < 8; i++) a[i] = As[(mg * 8 + i) * 33 + k];
            #pragma unroll
            for (int i = 0; i < 8; i++) {
                acc[i][0] = fmaf(a[i], b4.x, acc[i][0]);
                acc[i][1] = fmaf(a[i], b4.y, acc[i][1]);
                acc[i][2] = fmaf(a[i], b4.z, acc[i][2]);
                acc[i][3] = fmaf(a[i], b4.w, acc[i][3]);
            }
        }
        __syncthreads();
    }

    float* zp = g_zpart + ((size_t)s * BATCH + m0) * NOUT;
    #pragma unroll
    for (int i = 0; i < 8; i++) {
        float4 v = make_float4(acc[i][0], acc[i][1], acc[i][2], acc[i][3]);
        *(float4*)&zp[(mg * 8 + i) * NOUT + ng * 4] = v;
    }
}

// ---------------------------------------------------------------------------
// Kernel 3: sum split-K partials + bias, split mean / softplus(std)
// ---------------------------------------------------------------------------
__global__ __launch_bounds__(256) void finalize_kernel(
    const float* __restrict__ b_out, float* __restrict__ out)
{
    const int idx = blockIdx.x * 256 + threadIdx.x;
    if (idx >= BATCH * NOUT) return;
    const int b = idx >> 7;
    const int o = idx & 127;
    float z = __ldg(&b_out[o]);
    #pragma unroll
    for (int s = 0; s < SPLITK; s++)
        z += g_zpart[((size_t)s * BATCH + b) * NOUT + o];
    if (o < Z0) {
        out[(size_t)b * Z0 + o] = z;
    } else {
        // stable softplus: max(z,0) + log1p(exp(-|z|))
        const float sp = fmaxf(z, 0.f) + log1pf(expf(-fabsf(z)));
        out[(size_t)BATCH * Z0 + (size_t)b * Z0 + (o - Z0)] = sp;
    }
}

// ---------------------------------------------------------------------------
extern "C" void kernel_launch(void* const* d_in, const int* in_sizes, int n_in,
                              void* d_out, int out_size)
{
    const float* x    = (const float*)d_in[0];
    // d_in[1] = observed_tp (unused by the reference math)
    const float* w1   = (const float*)d_in[2];
    const float* b1   = (const float*)d_in[3];
    const float* w2   = (const float*)d_in[4];
    const float* b2   = (const float*)d_in[5];
    const float* w3   = (const float*)d_in[6];
    const float* b3   = (const float*)d_in[7];
    const float* wout = (const float*)d_in[8];
    const float* bout = (const float*)d_in[9];
    float* out = (float*)d_out;

    sig_kernel<<<BATCH, 512>>>(x, w1, b1, w2, b2, w3, b3);
    gemm_kernel<<<dim3(BATCH / BM, SPLITK), 256>>>(wout);
    finalize_kernel<<<(BATCH * NOUT + 255) / 256, 256>>>(bout, out);
}

// round 8
// speedup vs baseline: 1.6448x; 1.6448x over previous
#include <cuda_runtime.h>
#include <math.h>

#define BATCH 2048
#define LIN   70
#define DINC  15
#define HID   16
#define NF    4
#define KW    40
#define LP    31
#define CCH   20
#define SIGCH 8420
#define NOUT  128
#define Z0    64
#define SPLITK 16
#define KCHUNK 544          // 16*544 = 8704 >= 8420, 544 = 17*32

__device__ float g_sig[(size_t)BATCH * SIGCH];            // ~69 MB
__device__ float g_zpart[(size_t)SPLITK * BATCH * NOUT];  // ~17 MB

// ---- packed f32x2 helpers -------------------------------------------------
typedef unsigned long long ull;

__device__ __forceinline__ ull ffma2(ull a, ull b, ull c) {
    ull d;
    asm("fma.rn.f32x2 %0, %1, %2, %3;" : "=l"(d) : "l"(a), "l"(b), "l"(c));
    return d;
}
__device__ __forceinline__ ull pack2(float lo, float hi) {
    ull r;
    asm("mov.b64 %0, {%1, %2};" : "=l"(r) : "f"(lo), "f"(hi));
    return r;
}
__device__ __forceinline__ void unpack2(ull v, float& lo, float& hi) {
    asm("mov.b64 {%0, %1}, %2;" : "=f"(lo), "=f"(hi) : "l"(v));
}

// ---------------------------------------------------------------------------
// Kernel 1: fused conv stack + path + depth-3 signature. 1 CTA / batch.
// ---------------------------------------------------------------------------
#define XSTRIDE 20   // padded x row (floats): 16B-aligned, conflict-free
#define WSTRIDE 16   // padded w row (floats)

__global__ __launch_bounds__(512, 3) void sig_kernel(
    const float* __restrict__ x,    // (B, 70, 15)
    const float* __restrict__ w1,   // (16, 15, 40)
    const float* __restrict__ b1,
    const float* __restrict__ w2,   // (16, 16)
    const float* __restrict__ b2,
    const float* __restrict__ w3,   // (4, 16)
    const float* __restrict__ b3)
{
    __shared__ __align__(16) float sw1t[HID * KW * WSTRIDE]; // [o][k][c16] 40KB
    __shared__ __align__(16) float sxp[LIN * XSTRIDE];       // [l][c20]
    __shared__ float sh1[HID * LP];
    __shared__ float sh2[HID * LP];
    __shared__ __align__(16) float spath[LP * CCH];
    __shared__ __align__(16) float sdiff[LP * CCH];

    const int b   = blockIdx.x;
    const int tid = threadIdx.x;

    // ---- stage weights transposed + padded ----
    for (int i = tid; i < HID * DINC * KW; i += 512) {
        const int o = i / (DINC * KW);
        const int r = i - o * (DINC * KW);
        const int c = r / KW;
        const int k = r - c * KW;
        sw1t[(o * KW + k) * WSTRIDE + c] = w1[i];
    }
    // zero pads (c == 15)
    for (int i = tid; i < HID * KW; i += 512) sw1t[i * WSTRIDE + 15] = 0.f;

    // ---- stage x padded ----
    const float* xb = x + (size_t)b * (LIN * DINC);
    for (int i = tid; i < LIN * DINC; i += 512) {
        const int l = i / DINC, c = i - l * DINC;
        sxp[l * XSTRIDE + c] = xb[i];
    }
    if (tid < LIN) sxp[tid * XSTRIDE + 15] = 0.f;
    __syncthreads();

    // ---- conv1: full 16-channel f32x2 (4x ulonglong2 = 16 floats per row) ----
    if (tid < HID * LP) {
        const int o = tid / LP, l = tid - o * LP;
        ull acc[8];
        #pragma unroll
        for (int q = 0; q < 8; q++) acc[q] = 0ull;
        const float* wbase = sw1t + o * KW * WSTRIDE;
        #pragma unroll 4
        for (int k = 0; k < KW; k++) {
            const ulonglong2* xr = (const ulonglong2*)(sxp + (l + k) * XSTRIDE);
            const ulonglong2* wr = (const ulonglong2*)(wbase + k * WSTRIDE);
            ulonglong2 xv0 = xr[0], xv1 = xr[1], xv2 = xr[2], xv3 = xr[3];
            ulonglong2 wv0 = wr[0], wv1 = wr[1], wv2 = wr[2], wv3 = wr[3];
            acc[0] = ffma2(xv0.x, wv0.x, acc[0]);
            acc[1] = ffma2(xv0.y, wv0.y, acc[1]);
            acc[2] = ffma2(xv1.x, wv1.x, acc[2]);
            acc[3] = ffma2(xv1.y, wv1.y, acc[3]);
            acc[4] = ffma2(xv2.x, wv2.x, acc[4]);
            acc[5] = ffma2(xv2.y, wv2.y, acc[5]);
            acc[6] = ffma2(xv3.x, wv3.x, acc[6]);
            acc[7] = ffma2(xv3.y, wv3.y, acc[7]);
        }
        float s = 0.f;
        #pragma unroll
        for (int q = 0; q < 8; q++) {
            float lo, hi; unpack2(acc[q], lo, hi);
            s += lo + hi;
        }
        sh1[o * LP + l] = __ldg(&b1[o]) + s;
    }
    __syncthreads();

    // ---- conv2 ----
    if (tid < HID * LP) {
        const int o = tid / LP, l = tid - o * LP;
        float acc = __ldg(&b2[o]);
        #pragma unroll
        for (int c = 0; c < HID; c++)
            acc = fmaf(__ldg(&w2[o * HID + c]), fmaxf(sh1[c * LP + l], 0.f), acc);
        sh2[o * LP + l] = acc;
    }
    __syncthreads();

    // ---- conv3 + path ----
    for (int idx = tid; idx < LP * CCH; idx += 512) {
        const int l = idx / CCH, ch = idx - l * CCH;
        float v;
        if (ch < DINC) {
            v = sxp[(KW - 1 + l) * XSTRIDE + ch];
        } else if (ch == DINC) {
            v = (float)l * (1.0f / (float)(LP - 1));
        } else {
            const int f = ch - DINC - 1;
            float acc = __ldg(&b3[f]);
            #pragma unroll
            for (int c = 0; c < HID; c++)
                acc = fmaf(__ldg(&w3[f * HID + c]), fmaxf(sh2[c * LP + l], 0.f), acc);
            v = acc;
        }
        spath[idx] = v;
    }
    __syncthreads();

    // ---- increments (all steps up front) ----
    for (int idx = tid; idx < LP * CCH; idx += 512)
        sdiff[idx] = spath[idx] - (idx >= CCH ? spath[idx - CCH] : 0.f);
    __syncthreads();

    // ---- depth-3 signature, NO barriers inside ----
    if (tid < CCH * CCH) {
        const int ii = tid / CCH;
        const int jj = tid - ii * CCH;

        // peel t = 0 (s1 = 0, s2 = 0)
        float di = sdiff[ii];
        float dj = sdiff[jj];
        float t2 = di * dj * (1.f / 6.f);
        float s2r = 0.5f * di * dj;
        ull t2p = pack2(t2, t2);
        ull d3[10];
        {
            const ulonglong2* dv = (const ulonglong2*)sdiff;
            #pragma unroll
            for (int q = 0; q < 5; q++) {
                ulonglong2 dd = dv[q];
                d3[2 * q]     = ffma2(dd.x, t2p, 0ull);
                d3[2 * q + 1] = ffma2(dd.y, t2p, 0ull);
            }
        }

        #pragma unroll 5
        for (int t = 1; t < LP; t++) {
            di = sdiff[t * CCH + ii];
            dj = sdiff[t * CCH + jj];
            const float s1i = spath[(t - 1) * CCH + ii];
            t2 = fmaf(dj, fmaf(di, (1.f / 6.f), 0.5f * s1i), s2r);
            t2p = pack2(t2, t2);
            const ulonglong2* dv = (const ulonglong2*)(sdiff + t * CCH);
            #pragma unroll
            for (int q = 0; q < 5; q++) {
                ulonglong2 dd = dv[q];
                d3[2 * q]     = ffma2(dd.x, t2p, d3[2 * q]);
                d3[2 * q + 1] = ffma2(dd.y, t2p, d3[2 * q + 1]);
            }
            s2r = fmaf(dj, fmaf(0.5f, di, s1i), s2r);
        }

        // ---- emit ----
        float* sig = g_sig + (size_t)b * SIGCH;
        if (tid < CCH) sig[tid] = spath[(LP - 1) * CCH + tid];  // s1 = path[-1]
        sig[CCH + tid] = s2r;
        ulonglong2* dst = (ulonglong2*)(sig + CCH + CCH * CCH + tid * CCH);
        #pragma unroll
        for (int q = 0; q < 5; q++) {
            ulonglong2 v; v.x = d3[2 * q]; v.y = d3[2 * q + 1];
            dst[q] = v;
        }
    }
}

// ---------------------------------------------------------------------------
// Kernel 2: split-K GEMM with packed f32x2. BM=BN=128, BK=32, 256 thr, 8x8.
// ---------------------------------------------------------------------------
#define BM 128
#define BK 32
#define LDT 132   // padded tile stride

__global__ __launch_bounds__(256) void gemm_kernel(const float* __restrict__ W)
{
    __shared__ __align__(16) float As[BK * LDT];  // [k][m]
    __shared__ __align__(16) float Ws[BK * LDT];  // [k][o]

    const int m0  = blockIdx.x * BM;
    const int s   = blockIdx.y;
    const int kk0 = s * KCHUNK;
    const int kend = min(kk0 + KCHUNK, SIGCH);
    const int tid = threadIdx.x;
    const int mg  = tid >> 4;   // 0..15 -> rows mg*4, 64+mg*4
    const int ng  = tid & 15;   // 0..15 -> cols ng*4, 64+ng*4

    ull acc[8][4];
    #pragma unroll
    for (int i = 0; i < 8; i++)
        #pragma unroll
        for (int j = 0; j < 4; j++) acc[i][j] = 0ull;

    for (int kk = kk0; kk < kend; kk += BK) {
        // A tile: 128 rows x 8 float4 -> transposed store [k][m]
        #pragma unroll
        for (int u = 0; u < 4; u++) {
            const int idx = tid + u * 256;
            const int r = idx >> 3, q = idx & 7;
            const int c = kk + q * 4;
            float4 v = make_float4(0.f, 0.f, 0.f, 0.f);
            if (c < kend)
                v = *(const float4*)(g_sig + (size_t)(m0 + r) * SIGCH + c);
            As[(q * 4 + 0) * LDT + r] = v.x;
            As[(q * 4 + 1) * LDT + r] = v.y;
            As[(q * 4 + 2) * LDT + r] = v.z;
            As[(q * 4 + 3) * LDT + r] = v.w;
        }
        // W tile: 128 rows x 8 float4 -> transposed store [k][o]
        #pragma unroll
        for (int u = 0; u < 4; u++) {
            const int idx = tid + u * 256;
            const int o = idx >> 3, q = idx & 7;
            const int c = kk + q * 4;
            float4 v = make_float4(0.f, 0.f, 0.f, 0.f);
            if (c < kend)
                v = *(const float4*)(W + (size_t)o * SIGCH + c);
            Ws[(q * 4 + 0) * LDT + o] = v.x;
            Ws[(q * 4 + 1) * LDT + o] = v.y;
            Ws[(q * 4 + 2) * LDT + o] = v.z;
            Ws[(q * 4 + 3) * LDT + o] = v.w;
        }
        __syncthreads();

        #pragma unroll 8
        for (int k = 0; k < BK; k++) {
            const float4 a0 = *(const float4*)(As + k * LDT + mg * 4);
            const float4 a1 = *(const float4*)(As + k * LDT + 64 + mg * 4);
            const ulonglong2 b0 = *(const ulonglong2*)(Ws + k * LDT + ng * 4);
            const ulonglong2 b1 = *(const ulonglong2*)(Ws + k * LDT + 64 + ng * 4);
            ull ap[8];
            ap[0] = pack2(a0.x, a0.x); ap[1] = pack2(a0.y, a0.y);
            ap[2] = pack2(a0.z, a0.z); ap[3] = pack2(a0.w, a0.w);
            ap[4] = pack2(a1.x, a1.x); ap[5] = pack2(a1.y, a1.y);
            ap[6] = pack2(a1.z, a1.z); ap[7] = pack2(a1.w, a1.w);
            #pragma unroll
            for (int i = 0; i < 8; i++) {
                acc[i][0] = ffma2(ap[i], b0.x, acc[i][0]);
                acc[i][1] = ffma2(ap[i], b0.y, acc[i][1]);
                acc[i][2] = ffma2(ap[i], b1.x, acc[i][2]);
                acc[i][3] = ffma2(ap[i], b1.y, acc[i][3]);
            }
        }
        __syncthreads();
    }

    float* zp = g_zpart + ((size_t)s * BATCH + m0) * NOUT;
    #pragma unroll
    for (int i = 0; i < 8; i++) {
        const int m = (i < 4) ? (mg * 4 + i) : (64 + mg * 4 + (i - 4));
        ulonglong2 v0; v0.x = acc[i][0]; v0.y = acc[i][1];
        ulonglong2 v1; v1.x = acc[i][2]; v1.y = acc[i][3];
        *(ulonglong2*)(zp + m * NOUT + ng * 4) = v0;
        *(ulonglong2*)(zp + m * NOUT + 64 + ng * 4) = v1;
    }
}

// ---------------------------------------------------------------------------
// Kernel 3: reduce split-K + bias, mean / softplus
// ---------------------------------------------------------------------------
__global__ __launch_bounds__(256) void finalize_kernel(
    const float* __restrict__ b_out, float* __restrict__ out)
{
    const int idx = blockIdx.x * 256 + threadIdx.x;
    if (idx >= BATCH * NOUT) return;
    const int b = idx >> 7;
    const int o = idx & 127;
    float z = __ldg(&b_out[o]);
    #pragma unroll
    for (int s = 0; s < SPLITK; s++)
        z += g_zpart[((size_t)s * BATCH + b) * NOUT + o];
    if (o < Z0) {
        out[(size_t)b * Z0 + o] = z;
    } else {
        const float sp = fmaxf(z, 0.f) + log1pf(expf(-fabsf(z)));
        out[(size_t)BATCH * Z0 + (size_t)b * Z0 + (o - Z0)] = sp;
    }
}

// ---------------------------------------------------------------------------
extern "C" void kernel_launch(void* const* d_in, const int* in_sizes, int n_in,
                              void* d_out, int out_size)
{
    const float* x    = (const float*)d_in[0];
    const float* w1   = (const float*)d_in[2];
    const float* b1   = (const float*)d_in[3];
    const float* w2   = (const float*)d_in[4];
    const float* b2   = (const float*)d_in[5];
    const float* w3   = (const float*)d_in[6];
    const float* b3   = (const float*)d_in[7];
    const float* wout = (const float*)d_in[8];
    const float* bout = (const float*)d_in[9];
    float* out = (float*)d_out;

    sig_kernel<<<BATCH, 512>>>(x, w1, b1, w2, b2, w3, b3);
    gemm_kernel<<<dim3(BATCH / BM, SPLITK), 256>>>(wout);
    finalize_kernel<<<(BATCH * NOUT + 255) / 256, 256>>>(bout, out);
}

// round 9
// speedup vs baseline: 2.1069x; 1.2809x over previous
#include <cuda_runtime.h>
#include <math.h>

#define BATCH 2048
#define LIN   70
#define DINC  15
#define HID   16
#define NF    4
#define KW    40
#define LP    31
#define CCH   20
#define SIGCH 8420
#define NOUT  128
#define Z0    64
#define SPLITK 16
#define KCHUNK 544          // 16*544 = 8704 >= 8420, 544 = 17*32

__device__ float g_sig[(size_t)BATCH * SIGCH];            // ~69 MB
__device__ float g_zpart[(size_t)SPLITK * BATCH * NOUT];  // ~17 MB

// ---- packed f32x2 helpers -------------------------------------------------
typedef unsigned long long ull;

__device__ __forceinline__ ull ffma2(ull a, ull b, ull c) {
    ull d;
    asm("fma.rn.f32x2 %0, %1, %2, %3;" : "=l"(d) : "l"(a), "l"(b), "l"(c));
    return d;
}
__device__ __forceinline__ ull pack2(float lo, float hi) {
    ull r;
    asm("mov.b64 %0, {%1, %2};" : "=l"(r) : "f"(lo), "f"(hi));
    return r;
}
__device__ __forceinline__ void unpack2(ull v, float& lo, float& hi) {
    asm("mov.b64 {%0, %1}, %2;" : "=f"(lo), "=f"(hi) : "l"(v));
}

// ---------------------------------------------------------------------------
// Kernel 1: fused conv stack + path + depth-3 signature. 1 CTA / batch.
// ---------------------------------------------------------------------------
#define XTS 72   // transposed-x row stride (floats), even -> float2 aligned

__global__ __launch_bounds__(512, 3) void sig_kernel(
    const float* __restrict__ x,    // (B, 70, 15)
    const float* __restrict__ w1,   // (16, 15, 40) -- k contiguous
    const float* __restrict__ b1,
    const float* __restrict__ w2,   // (16, 16)
    const float* __restrict__ b2,
    const float* __restrict__ w3,   // (4, 16)
    const float* __restrict__ b3)
{
    __shared__ __align__(8)  float sw1[HID * DINC * KW];   // raw copy, 37.5KB
    __shared__ __align__(8)  float sxA[DINC * XTS];        // A[c][i] = x[i][c]
    __shared__ __align__(8)  float sxB[DINC * XTS];        // B[c][i] = x[i+1][c]
    __shared__ float sp1[2 * HID * 32];                    // k-split partials
    __shared__ float sh1[HID * LP];
    __shared__ float sh2[HID * LP];
    __shared__ __align__(16) float spath[LP * CCH];
    __shared__ __align__(16) float sdiff[LP * CCH];

    const int b   = blockIdx.x;
    const int tid = threadIdx.x;

    // ---- stage w1 raw + x transposed (plus one-shifted copy) ----
    for (int i = tid; i < HID * DINC * KW; i += 512) sw1[i] = w1[i];
    const float* xb = x + (size_t)b * (LIN * DINC);
    for (int idx = tid; idx < LIN * DINC; idx += 512) {
        const int l = idx / DINC, c = idx - l * DINC;
        const float v = xb[idx];
        sxA[c * XTS + l] = v;
        if (l) sxB[c * XTS + l - 1] = v;
    }
    __syncthreads();

    // ---- conv1: T=2 same-parity blocking, k-pair ffma2, k-split by 2 ----
    // tid = ks*256 + o*16 + par*8 + lg
    {
        const int ks  = tid >> 8;
        const int r   = tid & 255;
        const int o   = r >> 4;
        const int q   = r & 15;
        const int par = q >> 3;
        const int lg  = q & 7;
        const int l0  = 4 * lg + par;       // first output l
        const int k0  = ks * 20;            // k range [k0, k0+20)

        ull acc0 = 0ull, acc1 = 0ull;
        // base float index into the parity-matched array at k=0
        const float* xbase = par ? (sxB + (l0 - 1)) : (sxA + l0);
        const float* wbase = sw1 + o * (DINC * KW) + k0;

        #pragma unroll
        for (int c = 0; c < DINC; c++) {
            const ull* xp = (const ull*)(xbase + c * XTS + k0);
            const ull* wp = (const ull*)(wbase + c * KW);
            ull v = xp[0];
            #pragma unroll
            for (int kp = 0; kp < 10; kp++) {
                const ull wv = wp[kp];
                const ull vn = xp[kp + 1];
                acc0 = ffma2(v,  wv, acc0);
                acc1 = ffma2(vn, wv, acc1);
                v = vn;
            }
        }
        float a, bb, p0, p1;
        unpack2(acc0, a, bb); p0 = a + bb;
        unpack2(acc1, a, bb); p1 = a + bb;
        sp1[(ks * HID + o) * 32 + l0] = p0;
        if (l0 + 2 < LP)
            sp1[(ks * HID + o) * 32 + l0 + 2] = p1;
    }
    __syncthreads();

    // ---- combine k-split partials -> h1 ----
    if (tid < HID * LP) {
        const int o = tid / LP, l = tid - o * LP;
        sh1[tid] = __ldg(&b1[o]) + sp1[o * 32 + l] + sp1[(HID + o) * 32 + l];
    }
    __syncthreads();

    // ---- conv2 ----
    if (tid < HID * LP) {
        const int o = tid / LP, l = tid - o * LP;
        float acc = __ldg(&b2[o]);
        #pragma unroll
        for (int c = 0; c < HID; c++)
            acc = fmaf(__ldg(&w2[o * HID + c]), fmaxf(sh1[c * LP + l], 0.f), acc);
        sh2[o * LP + l] = acc;
    }
    __syncthreads();

    // ---- conv3 + path ----
    for (int idx = tid; idx < LP * CCH; idx += 512) {
        const int l = idx / CCH, ch = idx - l * CCH;
        float v;
        if (ch < DINC) {
            v = sxA[ch * XTS + (KW - 1 + l)];
        } else if (ch == DINC) {
            v = (float)l * (1.0f / (float)(LP - 1));
        } else {
            const int f = ch - DINC - 1;
            float acc = __ldg(&b3[f]);
            #pragma unroll
            for (int c = 0; c < HID; c++)
                acc = fmaf(__ldg(&w3[f * HID + c]), fmaxf(sh2[c * LP + l], 0.f), acc);
            v = acc;
        }
        spath[idx] = v;
    }
    __syncthreads();

    // ---- increments ----
    for (int idx = tid; idx < LP * CCH; idx += 512)
        sdiff[idx] = spath[idx] - (idx >= CCH ? spath[idx - CCH] : 0.f);
    __syncthreads();

    // ---- depth-3 signature, no barriers inside ----
    if (tid < CCH * CCH) {
        const int ii = tid / CCH;
        const int jj = tid - ii * CCH;

        // peel t = 0 (s1 = 0, s2 = 0)
        float di = sdiff[ii];
        float dj = sdiff[jj];
        float t2 = di * dj * (1.f / 6.f);
        float s2r = 0.5f * di * dj;
        ull t2p = pack2(t2, t2);
        ull d3[10];
        {
            const ulonglong2* dv = (const ulonglong2*)sdiff;
            #pragma unroll
            for (int qq = 0; qq < 5; qq++) {
                ulonglong2 dd = dv[qq];
                d3[2 * qq]     = ffma2(dd.x, t2p, 0ull);
                d3[2 * qq + 1] = ffma2(dd.y, t2p, 0ull);
            }
        }

        #pragma unroll 5
        for (int t = 1; t < LP; t++) {
            di = sdiff[t * CCH + ii];
            dj = sdiff[t * CCH + jj];
            const float s1i = spath[(t - 1) * CCH + ii];
            t2 = fmaf(dj, fmaf(di, (1.f / 6.f), 0.5f * s1i), s2r);
            t2p = pack2(t2, t2);
            const ulonglong2* dv = (const ulonglong2*)(sdiff + t * CCH);
            #pragma unroll
            for (int qq = 0; qq < 5; qq++) {
                ulonglong2 dd = dv[qq];
                d3[2 * qq]     = ffma2(dd.x, t2p, d3[2 * qq]);
                d3[2 * qq + 1] = ffma2(dd.y, t2p, d3[2 * qq + 1]);
            }
            s2r = fmaf(dj, fmaf(0.5f, di, s1i), s2r);
        }

        // ---- emit ----
        float* sig = g_sig + (size_t)b * SIGCH;
        if (tid < CCH) sig[tid] = spath[(LP - 1) * CCH + tid];  // s1 = path[-1]
        sig[CCH + tid] = s2r;
        ulonglong2* dst = (ulonglong2*)(sig + CCH + CCH * CCH + tid * CCH);
        #pragma unroll
        for (int qq = 0; qq < 5; qq++) {
            ulonglong2 v; v.x = d3[2 * qq]; v.y = d3[2 * qq + 1];
            dst[qq] = v;
        }
    }
}

// ---------------------------------------------------------------------------
// Kernel 2: split-K GEMM with packed f32x2. BM=BN=128, BK=32, 256 thr, 8x8.
// ---------------------------------------------------------------------------
#define BM 128
#define BK 32
#define LDT 132   // padded tile stride

__global__ __launch_bounds__(256) void gemm_kernel(const float* __restrict__ W)
{
    __shared__ __align__(16) float As[BK * LDT];  // [k][m]
    __shared__ __align__(16) float Ws[BK * LDT];  // [k][o]

    const int m0  = blockIdx.x * BM;
    const int s   = blockIdx.y;
    const int kk0 = s * KCHUNK;
    const int kend = min(kk0 + KCHUNK, SIGCH);
    const int tid = threadIdx.x;
    const int mg  = tid >> 4;   // 0..15 -> rows mg*4, 64+mg*4
    const int ng  = tid & 15;   // 0..15 -> cols ng*4, 64+ng*4

    ull acc[8][4];
    #pragma unroll
    for (int i = 0; i < 8; i++)
        #pragma unroll
        for (int j = 0; j < 4; j++) acc[i][j] = 0ull;

    for (int kk = kk0; kk < kend; kk += BK) {
        #pragma unroll
        for (int u = 0; u < 4; u++) {
            const int idx = tid + u * 256;
            const int r = idx >> 3, q = idx & 7;
            const int c = kk + q * 4;
            float4 v = make_float4(0.f, 0.f, 0.f, 0.f);
            if (c < kend)
                v = *(const float4*)(g_sig + (size_t)(m0 + r) * SIGCH + c);
            As[(q * 4 + 0) * LDT + r] = v.x;
            As[(q * 4 + 1) * LDT + r] = v.y;
            As[(q * 4 + 2) * LDT + r] = v.z;
            As[(q * 4 + 3) * LDT + r] = v.w;
        }
        #pragma unroll
        for (int u = 0; u < 4; u++) {
            const int idx = tid + u * 256;
            const int o = idx >> 3, q = idx & 7;
            const int c = kk + q * 4;
            float4 v = make_float4(0.f, 0.f, 0.f, 0.f);
            if (c < kend)
                v = *(const float4*)(W + (size_t)o * SIGCH + c);
            Ws[(q * 4 + 0) * LDT + o] = v.x;
            Ws[(q * 4 + 1) * LDT + o] = v.y;
            Ws[(q * 4 + 2) * LDT + o] = v.z;
            Ws[(q * 4 + 3) * LDT + o] = v.w;
        }
        __syncthreads();

        #pragma unroll 8
        for (int k = 0; k < BK; k++) {
            const float4 a0 = *(const float4*)(As + k * LDT + mg * 4);
            const float4 a1 = *(const float4*)(As + k * LDT + 64 + mg * 4);
            const ulonglong2 b0 = *(const ulonglong2*)(Ws + k * LDT + ng * 4);
            const ulonglong2 b1 = *(const ulonglong2*)(Ws + k * LDT + 64 + ng * 4);
            ull ap[8];
            ap[0] = pack2(a0.x, a0.x); ap[1] = pack2(a0.y, a0.y);
            ap[2] = pack2(a0.z, a0.z); ap[3] = pack2(a0.w, a0.w);
            ap[4] = pack2(a1.x, a1.x); ap[5] = pack2(a1.y, a1.y);
            ap[6] = pack2(a1.z, a1.z); ap[7] = pack2(a1.w, a1.w);
            #pragma unroll
            for (int i = 0; i < 8; i++) {
                acc[i][0] = ffma2(ap[i], b0.x, acc[i][0]);
                acc[i][1] = ffma2(ap[i], b0.y, acc[i][1]);
                acc[i][2] = ffma2(ap[i], b1.x, acc[i][2]);
                acc[i][3] = ffma2(ap[i], b1.y, acc[i][3]);
            }
        }
        __syncthreads();
    }

    float* zp = g_zpart + ((size_t)s * BATCH + m0) * NOUT;
    #pragma unroll
    for (int i = 0; i < 8; i++) {
        const int m = (i < 4) ? (mg * 4 + i) : (64 + mg * 4 + (i - 4));
        ulonglong2 v0; v0.x = acc[i][0]; v0.y = acc[i][1];
        ulonglong2 v1; v1.x = acc[i][2]; v1.y = acc[i][3];
        *(ulonglong2*)(zp + m * NOUT + ng * 4) = v0;
        *(ulonglong2*)(zp + m * NOUT + 64 + ng * 4) = v1;
    }
}

// ---------------------------------------------------------------------------
// Kernel 3: reduce split-K + bias, mean / softplus
// ---------------------------------------------------------------------------
__global__ __launch_bounds__(256) void finalize_kernel(
    const float* __restrict__ b_out, float* __restrict__ out)
{
    const int idx = blockIdx.x * 256 + threadIdx.x;
    if (idx >= BATCH * NOUT) return;
    const int b = idx >> 7;
    const int o = idx & 127;
    float z = __ldg(&b_out[o]);
    #pragma unroll
    for (int s = 0; s < SPLITK; s++)
        z += g_zpart[((size_t)s * BATCH + b) * NOUT + o];
    if (o < Z0) {
        out[(size_t)b * Z0 + o] = z;
    } else {
        const float sp = fmaxf(z, 0.f) + log1pf(expf(-fabsf(z)));
        out[(size_t)BATCH * Z0 + (size_t)b * Z0 + (o - Z0)] = sp;
    }
}

// ---------------------------------------------------------------------------
extern "C" void kernel_launch(void* const* d_in, const int* in_sizes, int n_in,
                              void* d_out, int out_size)
{
    const float* x    = (const float*)d_in[0];
    const float* w1   = (const float*)d_in[2];
    const float* b1   = (const float*)d_in[3];
    const float* w2   = (const float*)d_in[4];
    const float* b2   = (const float*)d_in[5];
    const float* w3   = (const float*)d_in[6];
    const float* b3   = (const float*)d_in[7];
    const float* wout = (const float*)d_in[8];
    const float* bout = (const float*)d_in[9];
    float* out = (float*)d_out;

    sig_kernel<<<BATCH, 512>>>(x, w1, b1, w2, b2, w3, b3);
    gemm_kernel<<<dim3(BATCH / BM, SPLITK), 256>>>(wout);
    finalize_kernel<<<(BATCH * NOUT + 255) / 256, 256>>>(bout, out);
}